// round 1
// baseline (speedup 1.0000x reference)
#include <cuda_runtime.h>
#include <mma.h>

using namespace nvcuda;

namespace {
constexpr int B  = 4;
constexpr int H  = 16;
constexpr int S  = 1024;   // SQ == SK
constexpr int D  = 1024;
constexpr int DK = 64;
constexpr int DV = 64;
constexpr int HB = H * B;
constexpr float INV_SCALE = 1.0f / 32.0f;   // 1/sqrt(D)
constexpr size_t OUT_ELEMS = (size_t)B * S * D;   // 4 * 1024 * 1024
}

// Scratch (allocation-free rule: __device__ globals)
__device__ float g_q[(size_t)B * H * S * DK];
__device__ float g_k[(size_t)B * H * S * DK];
__device__ float g_v[(size_t)B * H * S * DV];
__device__ float g_ctx[(size_t)B * S * H * DV];   // [b, q, h*dv]

using FragA  = wmma::fragment<wmma::matrix_a, 16, 16, 8, wmma::precision::tf32, wmma::row_major>;
using FragBr = wmma::fragment<wmma::matrix_b, 16, 16, 8, wmma::precision::tf32, wmma::row_major>;
using FragBc = wmma::fragment<wmma::matrix_b, 16, 16, 8, wmma::precision::tf32, wmma::col_major>;
using FragC  = wmma::fragment<wmma::accumulator, 16, 16, 8, float>;

template <typename F>
__device__ __forceinline__ void to_tf32(F& f) {
#pragma unroll
    for (int i = 0; i < f.num_elements; i++) f.x[i] = wmma::__float_to_tf32(f.x[i]);
}

// ---------------------------------------------------------------------------
// Kernel 1: QKV projections.
// C[bh][s][k] = sum_d X[b][s][d] * W[h][d][k]
// grid: (S/64, B*H, 3), block: 256 (8 warps; warp tile 32x16)
// ---------------------------------------------------------------------------
__global__ void __launch_bounds__(256)
proj_kernel(const float* __restrict__ xq, const float* __restrict__ xk,
            const float* __restrict__ xv, const float* __restrict__ wq,
            const float* __restrict__ wk, const float* __restrict__ wv)
{
    const int which = blockIdx.z;
    const int bh = blockIdx.y;
    const int b = bh / H, h = bh % H;

    const float* X = (which == 0) ? xq : (which == 1) ? xk : xv;
    const float* W = (which == 0) ? wq : (which == 1) ? wk : wv;
    float* Cb      = (which == 0) ? g_q : (which == 1) ? g_k : g_v;

    const float* A  = X + (size_t)b * S * D;          // [S, D], lda = D
    const float* Bm = W + (size_t)h * D * DK;         // [D, DK], ldb = DK
    float* C        = Cb + (size_t)bh * S * DK;       // [S, DK], ldc = DK
    const int m0 = blockIdx.x * 64;

    __shared__ float As[64][36];
    __shared__ float Bs[32][68];

    const int tid = threadIdx.x;
    const int warp = tid >> 5;
    const int wm = warp & 1;     // 0..1 -> 32 rows each
    const int wn = warp >> 1;    // 0..3 -> 16 cols each

    FragC acc[2];
    wmma::fill_fragment(acc[0], 0.0f);
    wmma::fill_fragment(acc[1], 0.0f);

    for (int k0 = 0; k0 < D; k0 += 32) {
        {   // A tile: 64 x 32
            int r = tid >> 3, c = (tid & 7) * 4;
            *(float4*)&As[r][c]      = *(const float4*)(A + (size_t)(m0 + r) * D + k0 + c);
            *(float4*)&As[r + 32][c] = *(const float4*)(A + (size_t)(m0 + r + 32) * D + k0 + c);
        }
        {   // B tile: 32 x 64
            int r = tid >> 4, c = (tid & 15) * 4;
            *(float4*)&Bs[r][c]      = *(const float4*)(Bm + (size_t)(k0 + r) * DK + c);
            *(float4*)&Bs[r + 16][c] = *(const float4*)(Bm + (size_t)(k0 + r + 16) * DK + c);
        }
        __syncthreads();
#pragma unroll
        for (int ks = 0; ks < 4; ks++) {
            FragA a0, a1; FragBr bf;
            wmma::load_matrix_sync(a0, &As[wm * 32][ks * 8], 36);
            wmma::load_matrix_sync(a1, &As[wm * 32 + 16][ks * 8], 36);
            wmma::load_matrix_sync(bf, &Bs[ks * 8][wn * 16], 68);
            to_tf32(a0); to_tf32(a1); to_tf32(bf);
            wmma::mma_sync(acc[0], a0, bf, acc[0]);
            wmma::mma_sync(acc[1], a1, bf, acc[1]);
        }
        __syncthreads();
    }
    wmma::store_matrix_sync(C + (size_t)(m0 + wm * 32) * DK + wn * 16,      acc[0], DK, wmma::mem_row_major);
    wmma::store_matrix_sync(C + (size_t)(m0 + wm * 32 + 16) * DK + wn * 16, acc[1], DK, wmma::mem_row_major);
}

// ---------------------------------------------------------------------------
// Kernel 2: scores = (q @ k^T) / 32, written straight into the attns output
// region in the reference layout [h][b][q][s].
// grid: (SQ/64, SK/64, B*H), block: 256
// ---------------------------------------------------------------------------
__global__ void __launch_bounds__(256)
scores_kernel(float* __restrict__ attn)
{
    const int bh = blockIdx.z;
    const int b = bh / H, h = bh % H;
    const float* q = g_q + (size_t)bh * S * DK;
    const float* k = g_k + (size_t)bh * S * DK;
    float* C = attn + ((size_t)(h * B + b) * S) * S;   // ldc = S

    const int q0 = blockIdx.x * 64;
    const int s0 = blockIdx.y * 64;

    __shared__ float Qs[64][68];
    __shared__ float Ks[64][68];

    const int tid = threadIdx.x;
    {
        int r = tid >> 4, c = (tid & 15) * 4;
#pragma unroll
        for (int i = 0; i < 4; i++) {
            int rr = r + i * 16;
            *(float4*)&Qs[rr][c] = *(const float4*)(q + (size_t)(q0 + rr) * DK + c);
            *(float4*)&Ks[rr][c] = *(const float4*)(k + (size_t)(s0 + rr) * DK + c);
        }
    }
    __syncthreads();

    const int warp = tid >> 5;
    const int wm = warp & 1, wn = warp >> 1;

    FragC acc[2];
    wmma::fill_fragment(acc[0], 0.0f);
    wmma::fill_fragment(acc[1], 0.0f);

#pragma unroll
    for (int ks = 0; ks < 8; ks++) {    // K = 64
        FragA a0, a1; FragBc bf;
        wmma::load_matrix_sync(a0, &Qs[wm * 32][ks * 8], 68);
        wmma::load_matrix_sync(a1, &Qs[wm * 32 + 16][ks * 8], 68);
        // B = k^T : element(kk, n) = Ks[n][kk]  -> col_major with ld 68
        wmma::load_matrix_sync(bf, &Ks[wn * 16][ks * 8], 68);
        to_tf32(a0); to_tf32(a1); to_tf32(bf);
        wmma::mma_sync(acc[0], a0, bf, acc[0]);
        wmma::mma_sync(acc[1], a1, bf, acc[1]);
    }
#pragma unroll
    for (int i = 0; i < acc[0].num_elements; i++) { acc[0].x[i] *= INV_SCALE; acc[1].x[i] *= INV_SCALE; }

    wmma::store_matrix_sync(C + (size_t)(q0 + wm * 32) * S + s0 + wn * 16,      acc[0], S, wmma::mem_row_major);
    wmma::store_matrix_sync(C + (size_t)(q0 + wm * 32 + 16) * S + s0 + wn * 16, acc[1], S, wmma::mem_row_major);
}

// ---------------------------------------------------------------------------
// Kernel 3: in-place row softmax over the attns region.
// grid: (SQ, H*B), block: 256 (each thread holds 4 values in registers)
// ---------------------------------------------------------------------------
__global__ void __launch_bounds__(256)
softmax_kernel(float* __restrict__ attn)
{
    __shared__ float red[8];
    const size_t row = (size_t)blockIdx.y * S + blockIdx.x;
    float* p = attn + row * S;

    float4 x = ((const float4*)p)[threadIdx.x];
    float m = fmaxf(fmaxf(x.x, x.y), fmaxf(x.z, x.w));
#pragma unroll
    for (int o = 16; o; o >>= 1) m = fmaxf(m, __shfl_xor_sync(0xffffffffu, m, o));
    const int warp = threadIdx.x >> 5, lane = threadIdx.x & 31;
    if (lane == 0) red[warp] = m;
    __syncthreads();
    float M = red[0];
#pragma unroll
    for (int i = 1; i < 8; i++) M = fmaxf(M, red[i]);
    __syncthreads();

    float e0 = __expf(x.x - M), e1 = __expf(x.y - M);
    float e2 = __expf(x.z - M), e3 = __expf(x.w - M);
    float s = (e0 + e1) + (e2 + e3);
#pragma unroll
    for (int o = 16; o; o >>= 1) s += __shfl_xor_sync(0xffffffffu, s, o);
    if (lane == 0) red[warp] = s;
    __syncthreads();
    float T = red[0];
#pragma unroll
    for (int i = 1; i < 8; i++) T += red[i];
    const float inv = 1.0f / T;

    x.x = e0 * inv; x.y = e1 * inv; x.z = e2 * inv; x.w = e3 * inv;
    ((float4*)p)[threadIdx.x] = x;
}

// ---------------------------------------------------------------------------
// Kernel 4: ctx = attn @ v, written in [b, q, h*dv] layout.
// grid: (S/64, B*H), block: 256
// ---------------------------------------------------------------------------
__global__ void __launch_bounds__(256)
pv_kernel(const float* __restrict__ attn)
{
    const int bh = blockIdx.y;
    const int b = bh / H, h = bh % H;

    const float* A  = attn + ((size_t)(h * B + b) * S) * S;  // [S, S], lda = S
    const float* Bm = g_v + (size_t)bh * S * DV;             // [S, DV], ldb = DV
    float* C = g_ctx + (size_t)b * S * H * DV + (size_t)h * DV;  // ldc = H*DV
    const int m0 = blockIdx.x * 64;

    __shared__ float As[64][36];
    __shared__ float Bs[32][68];

    const int tid = threadIdx.x;
    const int warp = tid >> 5;
    const int wm = warp & 1, wn = warp >> 1;

    FragC acc[2];
    wmma::fill_fragment(acc[0], 0.0f);
    wmma::fill_fragment(acc[1], 0.0f);

    for (int k0 = 0; k0 < S; k0 += 32) {
        {
            int r = tid >> 3, c = (tid & 7) * 4;
            *(float4*)&As[r][c]      = *(const float4*)(A + (size_t)(m0 + r) * S + k0 + c);
            *(float4*)&As[r + 32][c] = *(const float4*)(A + (size_t)(m0 + r + 32) * S + k0 + c);
        }
        {
            int r = tid >> 4, c = (tid & 15) * 4;
            *(float4*)&Bs[r][c]      = *(const float4*)(Bm + (size_t)(k0 + r) * DV + c);
            *(float4*)&Bs[r + 16][c] = *(const float4*)(Bm + (size_t)(k0 + r + 16) * DV + c);
        }
        __syncthreads();
#pragma unroll
        for (int ks = 0; ks < 4; ks++) {
            FragA a0, a1; FragBr bf;
            wmma::load_matrix_sync(a0, &As[wm * 32][ks * 8], 36);
            wmma::load_matrix_sync(a1, &As[wm * 32 + 16][ks * 8], 36);
            wmma::load_matrix_sync(bf, &Bs[ks * 8][wn * 16], 68);
            to_tf32(a0); to_tf32(a1); to_tf32(bf);
            wmma::mma_sync(acc[0], a0, bf, acc[0]);
            wmma::mma_sync(acc[1], a1, bf, acc[1]);
        }
        __syncthreads();
    }
    wmma::store_matrix_sync(C + (size_t)(m0 + wm * 32) * (H * DV) + wn * 16,      acc[0], H * DV, wmma::mem_row_major);
    wmma::store_matrix_sync(C + (size_t)(m0 + wm * 32 + 16) * (H * DV) + wn * 16, acc[1], H * DV, wmma::mem_row_major);
}

// ---------------------------------------------------------------------------
// Kernel 5: out = ctx @ w_proj^T   ([4096,1024] @ [1024,1024]^T)
// grid: (B*S/64, D/64), block: 256
// ---------------------------------------------------------------------------
__global__ void __launch_bounds__(256)
outproj_kernel(const float* __restrict__ wproj, float* __restrict__ out)
{
    const int m0 = blockIdx.x * 64;     // over B*S = 4096 rows
    const int n0 = blockIdx.y * 64;     // over D = 1024 cols

    __shared__ float As[64][36];
    __shared__ float Ws[64][36];        // Ws[n_local][k_local] = wproj[n0+n][k0+k]

    const int tid = threadIdx.x;
    const int warp = tid >> 5;
    const int wm = warp & 1, wn = warp >> 1;

    FragC acc[2];
    wmma::fill_fragment(acc[0], 0.0f);
    wmma::fill_fragment(acc[1], 0.0f);

    for (int k0 = 0; k0 < H * DV; k0 += 32) {
        {
            int r = tid >> 3, c = (tid & 7) * 4;
            *(float4*)&As[r][c]      = *(const float4*)(g_ctx + (size_t)(m0 + r) * (H * DV) + k0 + c);
            *(float4*)&As[r + 32][c] = *(const float4*)(g_ctx + (size_t)(m0 + r + 32) * (H * DV) + k0 + c);
            *(float4*)&Ws[r][c]      = *(const float4*)(wproj + (size_t)(n0 + r) * (H * DV) + k0 + c);
            *(float4*)&Ws[r + 32][c] = *(const float4*)(wproj + (size_t)(n0 + r + 32) * (H * DV) + k0 + c);
        }
        __syncthreads();
#pragma unroll
        for (int ks = 0; ks < 4; ks++) {
            FragA a0, a1; FragBc bf;
            wmma::load_matrix_sync(a0, &As[wm * 32][ks * 8], 36);
            wmma::load_matrix_sync(a1, &As[wm * 32 + 16][ks * 8], 36);
            // B^T: element(kk, n) = Ws[n][kk] -> col_major, ld 36
            wmma::load_matrix_sync(bf, &Ws[wn * 16][ks * 8], 36);
            to_tf32(a0); to_tf32(a1); to_tf32(bf);
            wmma::mma_sync(acc[0], a0, bf, acc[0]);
            wmma::mma_sync(acc[1], a1, bf, acc[1]);
        }
        __syncthreads();
    }
    wmma::store_matrix_sync(out + (size_t)(m0 + wm * 32) * D + n0 + wn * 16,      acc[0], D, wmma::mem_row_major);
    wmma::store_matrix_sync(out + (size_t)(m0 + wm * 32 + 16) * D + n0 + wn * 16, acc[1], D, wmma::mem_row_major);
}

// ---------------------------------------------------------------------------
// Kernel 6: out[i] += b_proj[i % D]   (bias is zeros in the dataset, but keep
// the math faithful to the reference)
// ---------------------------------------------------------------------------
__global__ void __launch_bounds__(1024)
bias_kernel(float* __restrict__ out, const float* __restrict__ bias)
{
    size_t i = (size_t)blockIdx.x * 1024 + threadIdx.x;
    out[i] += bias[threadIdx.x];
}

// ---------------------------------------------------------------------------

extern "C" void kernel_launch(void* const* d_in, const int* in_sizes, int n_in,
                              void* d_out, int out_size)
{
    const float* query  = (const float*)d_in[0];
    const float* key    = (const float*)d_in[1];
    const float* value  = (const float*)d_in[2];
    const float* w_q    = (const float*)d_in[3];
    const float* w_k    = (const float*)d_in[4];
    const float* w_v    = (const float*)d_in[5];
    const float* w_proj = (const float*)d_in[6];
    const float* b_proj = (const float*)d_in[7];

    float* out  = (float*)d_out;            // [B, S, D]
    float* attn = out + OUT_ELEMS;          // [H*B, S, S]

    proj_kernel<<<dim3(S / 64, HB, 3), 256>>>(query, key, value, w_q, w_k, w_v);
    scores_kernel<<<dim3(S / 64, S / 64, HB), 256>>>(attn);
    softmax_kernel<<<dim3(S, HB), 256>>>(attn);
    pv_kernel<<<dim3(S / 64, HB), 256>>>(attn);
    outproj_kernel<<<dim3(B * S / 64, D / 64), 256>>>(w_proj, out);
    bias_kernel<<<B * S, 1024>>>(out, b_proj);
}